// round 14
// baseline (speedup 1.0000x reference)
#include <cuda_runtime.h>

#define T_DIM 3
#define B_DIM 100000
#define D_DIM 128
#define NEG_SLOPE 0.01f
#define TOTAL_ROWS (T_DIM * B_DIM)

// 256-bit (v8.f32) streaming load/store helpers — sm_100+ LDG.E.256 path.
__device__ __forceinline__ void ldcs256(const float* __restrict__ p, float r[8]) {
    asm volatile("ld.global.cs.v8.f32 {%0,%1,%2,%3,%4,%5,%6,%7}, [%8];"
                 : "=f"(r[0]), "=f"(r[1]), "=f"(r[2]), "=f"(r[3]),
                   "=f"(r[4]), "=f"(r[5]), "=f"(r[6]), "=f"(r[7])
                 : "l"(p));
}
__device__ __forceinline__ void ldg256(const float* __restrict__ p, float r[8]) {
    asm volatile("ld.global.nc.v8.f32 {%0,%1,%2,%3,%4,%5,%6,%7}, [%8];"
                 : "=f"(r[0]), "=f"(r[1]), "=f"(r[2]), "=f"(r[3]),
                   "=f"(r[4]), "=f"(r[5]), "=f"(r[6]), "=f"(r[7])
                 : "l"(p));
}
__device__ __forceinline__ void stcs256(float* __restrict__ p, const float r[8]) {
    asm volatile("st.global.cs.v8.f32 [%0], {%1,%2,%3,%4,%5,%6,%7,%8};"
                 :: "l"(p),
                    "f"(r[0]), "f"(r[1]), "f"(r[2]), "f"(r[3]),
                    "f"(r[4]), "f"(r[5]), "f"(r[6]), "f"(r[7])
                 : "memory");
}

// One warp per PAIR of consecutive (t,b) rows; each lane owns 8 consecutive
// floats (256-bit). Lanes 0-15 cover row0, lanes 16-31 cover row1. Each big
// stream is ONE v8 load per lane. NEW: the issue order of the 4 big streams
// is rotated by warp id so the chip-wide instantaneous request mix covers all
// four ~51MB-apart regions uniformly (steadier open-row mix per controller).
__global__ __launch_bounds__(512, 2)
void attconv_kernel(const float* __restrict__ h_center,   // (T*B*128)
                    const float* __restrict__ h_neigh,    // (T*T*B*128)
                    const float* __restrict__ att_w,      // (T*256)
                    const float* __restrict__ att_b,      // (T)
                    float* __restrict__ out)              // (T*B*128)
{
    const int gwarp = (blockIdx.x * blockDim.x + threadIdx.x) >> 5;
    const int lane  = threadIdx.x & 31;
    const int row0  = gwarp * 2;                 // first row of the pair
    if (row0 >= TOTAL_ROWS) return;

    const int t  = row0 / B_DIM;                 // same t for both rows
    const int b0 = row0 - t * B_DIM;
    const int hl = lane & 15;                    // position within the row

    const long ctr_off = (long)row0 * 128 + lane * 8;
    const long nb_base = ((long)(t * T_DIM) * B_DIM + b0) * 128 + lane * 8;
    const long nstride = (long)B_DIM * 128;

    // Stream pointers: 0 = center, 1..3 = neighbors.
    const float* sp[4];
    sp[0] = h_center + ctr_off;
    sp[1] = h_neigh + nb_base;
    sp[2] = h_neigh + nb_base + nstride;
    sp[3] = h_neigh + nb_base + 2 * nstride;

    // Rotate issue order by warp id (stagger streams chip-wide).
    const int rot = gwarp & 3;
    float buf[4][8];
    #pragma unroll
    for (int k = 0; k < 4; k++) {
        const int s = (k + rot) & 3;
        ldcs256(sp[s], buf[s]);
    }
    float* c  = buf[0];
    float* v0 = buf[1];
    float* v1 = buf[2];
    float* v2 = buf[3];

    float wh[8], we[8];
    ldg256(att_w + t * 256 + hl * 8, wh);
    ldg256(att_w + t * 256 + 128 + hl * 8, we);
    const float bias = __ldg(att_b + t);

    // Per-lane partials over this lane's 8 floats; score_h folded in.
    float ph = 0.f, p0 = 0.f, p1 = 0.f, p2 = 0.f, p3 = 0.f;
    #pragma unroll
    for (int i = 0; i < 8; i++) {
        ph += c[i] * wh[i];
        p0 += v0[i] * we[i];
        p1 += v1[i] * we[i];
        p2 += v2[i] * we[i];
        p3 += c[i] * we[i];
    }
    p0 += ph; p1 += ph; p2 += ph; p3 += ph;

    // Butterfly within each 16-lane half (off<=8 never crosses halves).
    #pragma unroll
    for (int off = 8; off > 0; off >>= 1) {
        p0 += __shfl_xor_sync(0xFFFFFFFFu, p0, off);
        p1 += __shfl_xor_sync(0xFFFFFFFFu, p1, off);
        p2 += __shfl_xor_sync(0xFFFFFFFFu, p2, off);
        p3 += __shfl_xor_sync(0xFFFFFFFFu, p3, off);
    }

    // Each half holds its own row's 4 scores. Softmax per half.
    float s0 = p0 + bias, s1 = p1 + bias, s2 = p2 + bias, s3 = p3 + bias;
    s0 = (s0 >= 0.f) ? s0 : NEG_SLOPE * s0;
    s1 = (s1 >= 0.f) ? s1 : NEG_SLOPE * s1;
    s2 = (s2 >= 0.f) ? s2 : NEG_SLOPE * s2;
    s3 = (s3 >= 0.f) ? s3 : NEG_SLOPE * s3;
    float m = fmaxf(fmaxf(s0, s1), fmaxf(s2, s3));
    float e0 = __expf(s0 - m), e1 = __expf(s1 - m);
    float e2 = __expf(s2 - m), e3 = __expf(s3 - m);
    float inv = __fdividef(1.0f, e0 + e1 + e2 + e3);
    float w0 = e0 * inv, w1 = e1 * inv, w2 = e2 * inv, w3 = e3 * inv;

    // Weighted sum over this lane's 8 floats; one 256-bit store.
    float o[8];
    #pragma unroll
    for (int i = 0; i < 8; i++)
        o[i] = w0 * v0[i] + w1 * v1[i] + w2 * v2[i] + w3 * c[i];
    stcs256(out + ctr_off, o);
}

extern "C" void kernel_launch(void* const* d_in, const int* in_sizes, int n_in,
                              void* d_out, int out_size) {
    const float* h_center = (const float*)d_in[0];
    const float* h_neigh  = (const float*)d_in[1];
    const float* att_w    = (const float*)d_in[2];
    const float* att_b    = (const float*)d_in[3];
    float* out = (float*)d_out;

    const int total_pairs = TOTAL_ROWS / 2;             // 150000 warps
    const int threads = 512;                            // 16 warps/block
    const int blocks = (total_pairs * 32 + threads - 1) / threads;  // 9375

    attconv_kernel<<<blocks, threads>>>(h_center, h_neigh, att_w, att_b, out);
}

// round 15
// speedup vs baseline: 1.5425x; 1.5425x over previous
#include <cuda_runtime.h>

#define T_DIM 3
#define B_DIM 100000
#define D_DIM 128
#define NEG_SLOPE 0.01f
#define TOTAL_ROWS (T_DIM * B_DIM)

// FINAL kernel (R13 config — best measured profile: 106.1us ncu, 89.4% DRAM,
// 7084 GB/s). All axes swept: pair-per-warp, 512-thread CTAs, one-shot grid,
// .cs streaming, 256-bit v8 loads/stores, static register arrays only
// (runtime-indexed arrays spill to local memory — measured 1.55x regression).

// 256-bit (v8.f32) streaming load/store helpers — sm_100+ LDG.E.256 path.
__device__ __forceinline__ void ldcs256(const float* __restrict__ p, float r[8]) {
    asm volatile("ld.global.cs.v8.f32 {%0,%1,%2,%3,%4,%5,%6,%7}, [%8];"
                 : "=f"(r[0]), "=f"(r[1]), "=f"(r[2]), "=f"(r[3]),
                   "=f"(r[4]), "=f"(r[5]), "=f"(r[6]), "=f"(r[7])
                 : "l"(p));
}
__device__ __forceinline__ void ldg256(const float* __restrict__ p, float r[8]) {
    asm volatile("ld.global.nc.v8.f32 {%0,%1,%2,%3,%4,%5,%6,%7}, [%8];"
                 : "=f"(r[0]), "=f"(r[1]), "=f"(r[2]), "=f"(r[3]),
                   "=f"(r[4]), "=f"(r[5]), "=f"(r[6]), "=f"(r[7])
                 : "l"(p));
}
__device__ __forceinline__ void stcs256(float* __restrict__ p, const float r[8]) {
    asm volatile("st.global.cs.v8.f32 [%0], {%1,%2,%3,%4,%5,%6,%7,%8};"
                 :: "l"(p),
                    "f"(r[0]), "f"(r[1]), "f"(r[2]), "f"(r[3]),
                    "f"(r[4]), "f"(r[5]), "f"(r[6]), "f"(r[7])
                 : "memory");
}

// One warp per PAIR of consecutive (t,b) rows; each lane owns 8 consecutive
// floats (256-bit). Lanes 0-15 cover row0, lanes 16-31 cover row1. Each big
// stream is ONE v8 load per lane (1KB contiguous per warp instruction).
// Dot-product reduction is a 4-stage butterfly within each 16-lane half.
__global__ __launch_bounds__(512, 2)
void attconv_kernel(const float* __restrict__ h_center,   // (T*B*128)
                    const float* __restrict__ h_neigh,    // (T*T*B*128)
                    const float* __restrict__ att_w,      // (T*256)
                    const float* __restrict__ att_b,      // (T)
                    float* __restrict__ out)              // (T*B*128)
{
    const int gwarp = (blockIdx.x * blockDim.x + threadIdx.x) >> 5;
    const int lane  = threadIdx.x & 31;
    const int row0  = gwarp * 2;                 // first row of the pair
    if (row0 >= TOTAL_ROWS) return;

    const int t  = row0 / B_DIM;                 // same t for both rows
    const int b0 = row0 - t * B_DIM;
    const int hl = lane & 15;                    // position within the row

    // Float offsets: lane*8 spans the 256-float (2-row) pair block.
    const long ctr_off = (long)row0 * 128 + lane * 8;
    const long nb_base = ((long)(t * T_DIM) * B_DIM + b0) * 128 + lane * 8;
    const long nstride = (long)B_DIM * 128;

    // 4 big streaming loads (1KB/warp each) + 2 cached weight loads.
    float c[8], v0[8], v1[8], v2[8], wh[8], we[8];
    ldcs256(h_center + ctr_off, c);
    ldcs256(h_neigh + nb_base + 0 * nstride, v0);
    ldcs256(h_neigh + nb_base + 1 * nstride, v1);
    ldcs256(h_neigh + nb_base + 2 * nstride, v2);
    ldg256(att_w + t * 256 + hl * 8, wh);        // w_h chunk for this lane
    ldg256(att_w + t * 256 + 128 + hl * 8, we);  // w_e chunk for this lane
    const float bias = __ldg(att_b + t);

    // Per-lane partials over this lane's 8 floats; score_h folded in.
    float ph = 0.f, p0 = 0.f, p1 = 0.f, p2 = 0.f, p3 = 0.f;
    #pragma unroll
    for (int i = 0; i < 8; i++) {
        ph += c[i] * wh[i];
        p0 += v0[i] * we[i];
        p1 += v1[i] * we[i];
        p2 += v2[i] * we[i];
        p3 += c[i] * we[i];
    }
    p0 += ph; p1 += ph; p2 += ph; p3 += ph;

    // Butterfly within each 16-lane half (off=1,2,4,8 never crosses halves).
    #pragma unroll
    for (int off = 8; off > 0; off >>= 1) {
        p0 += __shfl_xor_sync(0xFFFFFFFFu, p0, off);
        p1 += __shfl_xor_sync(0xFFFFFFFFu, p1, off);
        p2 += __shfl_xor_sync(0xFFFFFFFFu, p2, off);
        p3 += __shfl_xor_sync(0xFFFFFFFFu, p3, off);
    }

    // Each half now holds its own row's 4 scores. Softmax per half.
    float s0 = p0 + bias, s1 = p1 + bias, s2 = p2 + bias, s3 = p3 + bias;
    s0 = (s0 >= 0.f) ? s0 : NEG_SLOPE * s0;
    s1 = (s1 >= 0.f) ? s1 : NEG_SLOPE * s1;
    s2 = (s2 >= 0.f) ? s2 : NEG_SLOPE * s2;
    s3 = (s3 >= 0.f) ? s3 : NEG_SLOPE * s3;
    float m = fmaxf(fmaxf(s0, s1), fmaxf(s2, s3));
    float e0 = __expf(s0 - m), e1 = __expf(s1 - m);
    float e2 = __expf(s2 - m), e3 = __expf(s3 - m);
    float inv = __fdividef(1.0f, e0 + e1 + e2 + e3);
    float w0 = e0 * inv, w1 = e1 * inv, w2 = e2 * inv, w3 = e3 * inv;

    // Weighted sum over this lane's 8 floats; one 256-bit store.
    float o[8];
    #pragma unroll
    for (int i = 0; i < 8; i++)
        o[i] = w0 * v0[i] + w1 * v1[i] + w2 * v2[i] + w3 * c[i];
    stcs256(out + ctr_off, o);
}

extern "C" void kernel_launch(void* const* d_in, const int* in_sizes, int n_in,
                              void* d_out, int out_size) {
    const float* h_center = (const float*)d_in[0];
    const float* h_neigh  = (const float*)d_in[1];
    const float* att_w    = (const float*)d_in[2];
    const float* att_b    = (const float*)d_in[3];
    float* out = (float*)d_out;

    const int total_pairs = TOTAL_ROWS / 2;             // 150000 warps
    const int threads = 512;                            // 16 warps/block
    const int blocks = (total_pairs * 32 + threads - 1) / threads;  // 9375

    attconv_kernel<<<blocks, threads>>>(h_center, h_neigh, att_w, att_b, out);
}

// round 17
// speedup vs baseline: 1.5556x; 1.0085x over previous
#include <cuda_runtime.h>

#define T_DIM 3
#define B_DIM 100000
#define D_DIM 128
#define NEG_SLOPE 0.01f
#define TOTAL_ROWS (T_DIM * B_DIM)

// R13-class kernel (best measured profile: ~106.1us ncu, ~89% DRAM, ~7.1TB/s).
// Pair-per-warp, 512-thread CTAs, one-shot grid, 256-bit v8 accesses.
// This round: .cs kept on loads (zero reuse), default write-back on the
// output store (let L2 batch dirty-line drains instead of evict-first).

__device__ __forceinline__ void ldcs256(const float* __restrict__ p, float r[8]) {
    asm volatile("ld.global.cs.v8.f32 {%0,%1,%2,%3,%4,%5,%6,%7}, [%8];"
                 : "=f"(r[0]), "=f"(r[1]), "=f"(r[2]), "=f"(r[3]),
                   "=f"(r[4]), "=f"(r[5]), "=f"(r[6]), "=f"(r[7])
                 : "l"(p));
}
__device__ __forceinline__ void ldg256(const float* __restrict__ p, float r[8]) {
    asm volatile("ld.global.nc.v8.f32 {%0,%1,%2,%3,%4,%5,%6,%7}, [%8];"
                 : "=f"(r[0]), "=f"(r[1]), "=f"(r[2]), "=f"(r[3]),
                   "=f"(r[4]), "=f"(r[5]), "=f"(r[6]), "=f"(r[7])
                 : "l"(p));
}
__device__ __forceinline__ void st256(float* __restrict__ p, const float r[8]) {
    asm volatile("st.global.v8.f32 [%0], {%1,%2,%3,%4,%5,%6,%7,%8};"
                 :: "l"(p),
                    "f"(r[0]), "f"(r[1]), "f"(r[2]), "f"(r[3]),
                    "f"(r[4]), "f"(r[5]), "f"(r[6]), "f"(r[7])
                 : "memory");
}

// One warp per PAIR of consecutive (t,b) rows; each lane owns 8 consecutive
// floats (256-bit). Lanes 0-15 cover row0, lanes 16-31 cover row1. Each big
// stream is ONE v8 load per lane (1KB contiguous per warp instruction).
// Dot-product reduction is a 4-stage butterfly within each 16-lane half.
// NOTE: static register arrays only — runtime-indexed arrays spill to local
// memory (measured 1.55x regression in R14).
__global__ __launch_bounds__(512, 2)
void attconv_kernel(const float* __restrict__ h_center,   // (T*B*128)
                    const float* __restrict__ h_neigh,    // (T*T*B*128)
                    const float* __restrict__ att_w,      // (T*256)
                    const float* __restrict__ att_b,      // (T)
                    float* __restrict__ out)              // (T*B*128)
{
    const int gwarp = (blockIdx.x * blockDim.x + threadIdx.x) >> 5;
    const int lane  = threadIdx.x & 31;
    const int row0  = gwarp * 2;                 // first row of the pair
    if (row0 >= TOTAL_ROWS) return;

    const int t  = row0 / B_DIM;                 // same t for both rows
    const int b0 = row0 - t * B_DIM;
    const int hl = lane & 15;                    // position within the row

    // Float offsets: lane*8 spans the 256-float (2-row) pair block.
    const long ctr_off = (long)row0 * 128 + lane * 8;
    const long nb_base = ((long)(t * T_DIM) * B_DIM + b0) * 128 + lane * 8;
    const long nstride = (long)B_DIM * 128;

    // 4 big streaming loads (1KB/warp each) + 2 cached weight loads.
    float c[8], v0[8], v1[8], v2[8], wh[8], we[8];
    ldcs256(h_center + ctr_off, c);
    ldcs256(h_neigh + nb_base + 0 * nstride, v0);
    ldcs256(h_neigh + nb_base + 1 * nstride, v1);
    ldcs256(h_neigh + nb_base + 2 * nstride, v2);
    ldg256(att_w + t * 256 + hl * 8, wh);        // w_h chunk for this lane
    ldg256(att_w + t * 256 + 128 + hl * 8, we);  // w_e chunk for this lane
    const float bias = __ldg(att_b + t);

    // Per-lane partials over this lane's 8 floats; score_h folded in.
    float ph = 0.f, p0 = 0.f, p1 = 0.f, p2 = 0.f, p3 = 0.f;
    #pragma unroll
    for (int i = 0; i < 8; i++) {
        ph += c[i] * wh[i];
        p0 += v0[i] * we[i];
        p1 += v1[i] * we[i];
        p2 += v2[i] * we[i];
        p3 += c[i] * we[i];
    }
    p0 += ph; p1 += ph; p2 += ph; p3 += ph;

    // Butterfly within each 16-lane half (off=1,2,4,8 never crosses halves).
    #pragma unroll
    for (int off = 8; off > 0; off >>= 1) {
        p0 += __shfl_xor_sync(0xFFFFFFFFu, p0, off);
        p1 += __shfl_xor_sync(0xFFFFFFFFu, p1, off);
        p2 += __shfl_xor_sync(0xFFFFFFFFu, p2, off);
        p3 += __shfl_xor_sync(0xFFFFFFFFu, p3, off);
    }

    // Each half now holds its own row's 4 scores. Softmax per half.
    float s0 = p0 + bias, s1 = p1 + bias, s2 = p2 + bias, s3 = p3 + bias;
    s0 = (s0 >= 0.f) ? s0 : NEG_SLOPE * s0;
    s1 = (s1 >= 0.f) ? s1 : NEG_SLOPE * s1;
    s2 = (s2 >= 0.f) ? s2 : NEG_SLOPE * s2;
    s3 = (s3 >= 0.f) ? s3 : NEG_SLOPE * s3;
    float m = fmaxf(fmaxf(s0, s1), fmaxf(s2, s3));
    float e0 = __expf(s0 - m), e1 = __expf(s1 - m);
    float e2 = __expf(s2 - m), e3 = __expf(s3 - m);
    float inv = __fdividef(1.0f, e0 + e1 + e2 + e3);
    float w0 = e0 * inv, w1 = e1 * inv, w2 = e2 * inv, w3 = e3 * inv;

    // Weighted sum over this lane's 8 floats; one 256-bit store (write-back).
    float o[8];
    #pragma unroll
    for (int i = 0; i < 8; i++)
        o[i] = w0 * v0[i] + w1 * v1[i] + w2 * v2[i] + w3 * c[i];
    st256(out + ctr_off, o);
}

extern "C" void kernel_launch(void* const* d_in, const int* in_sizes, int n_in,
                              void* d_out, int out_size) {
    const float* h_center = (const float*)d_in[0];
    const float* h_neigh  = (const float*)d_in[1];
    const float* att_w    = (const float*)d_in[2];
    const float* att_b    = (const float*)d_in[3];
    float* out = (float*)d_out;

    const int total_pairs = TOTAL_ROWS / 2;             // 150000 warps
    const int threads = 512;                            // 16 warps/block
    const int blocks = (total_pairs * 32 + threads - 1) / threads;  // 9375

    attconv_kernel<<<blocks, threads>>>(h_center, h_neigh, att_w, att_b, out);
}